// round 15
// baseline (speedup 1.0000x reference)
#include <cuda_runtime.h>

#define NN 500000
#define NE 8000000
#define TPB 256
#define NB_N ((NN + TPB - 1) / TPB)
#define CAP 64   // Poisson(16) in-degree: P(deg>=64) ~ 1e-20 — clamp for safety

// ---------------- scratch (static __device__ — no allocation) ----------------
__device__ int    g_cnt [NN];          // in-degree counter / scatter cursor
__device__ int    g_bkt [NN * CAP];    // per-dst src lists (128 MB)
__device__ float  g_dinv[NN];          // 1/(deg+1)
__device__ float  g_sqd [NN];          // sqrt(deg+1)
__device__ float2 g_s0[NN], g_s1[NN], g_s2[NN], g_s3[NN];  // s_k = dsr*(u_k, v_k)
__device__ float  g_R  [128];          // R1,R2,R3,R4 (each 32) — collapsed weight rows

// ---------------- weights in constant memory ----------------
__constant__ float c_w[736];
#define W1_OFF 0
#define B1_OFF 4
#define W2_OFF 8
#define B2_OFF 40
#define W3_OFF 48
#define B3_OFF 176
#define W4_OFF 192
#define B4_OFF 704

// Compile-time s_k selection (device-side symbol refs only — R8 lesson).
template<int K> __device__ __forceinline__ float2* s_ptr() {
    if (K == 0) return g_s0;
    if (K == 1) return g_s1;
    if (K == 2) return g_s2;
    return g_s3;
}

// ---------------- kernels ----------------
__global__ void k_zero() {
    int i = blockIdx.x * TPB + threadIdx.x;
    if (i < NN) g_cnt[i] = 0;
}

// bucket scatter: group src indices by dst; count doubles as degree
__global__ void k_scatter(const int* __restrict__ src, const int* __restrict__ dst) {
    int e = blockIdx.x * TPB + threadIdx.x;
    if (e >= NE) return;
    int d = dst[e];
    int p = atomicAdd(&g_cnt[d], 1);
    if (p < CAP) g_bkt[d * CAP + p] = src[e];
}

// degree terms + s0 (reads g_cnt AFTER scatter)
__global__ void k_node1(const int* __restrict__ rl) {
    int i = blockIdx.x * TPB + threadIdx.x;
    if (i >= NN) return;
    float deg = (float)g_cnt[i] + 1.0f;
    float ds  = rsqrtf(deg);
    g_dinv[i] = 1.0f / deg;
    g_sqd[i]  = sqrtf(deg);
    g_s0[i]   = make_float2((float)rl[i] * (1.0f / 20000.0f) * ds, ds);
}

// pull pass K: s_{K+1}[i] = dinv_i * (s_K[i] + sum_{j->i} s_K[j]) — no atomics
template<int K>
__global__ void k_pull() {
    int i = blockIdx.x * TPB + threadIdx.x;
    if (i >= NN) return;
    const float2* __restrict__ s = s_ptr<K>();
    int n   = min(g_cnt[i], CAP);
    const int* __restrict__ row = g_bkt + i * CAP;
    float2 self = s[i];
    float ax = self.x, ay = self.y;
    float bx = 0.f, by = 0.f, cx = 0.f, cy = 0.f, dx = 0.f, dy = 0.f;
    int j = 0;
    for (; j + 3 < n; j += 4) {                 // 4-way MLP
        int n0 = row[j], n1 = row[j + 1], n2 = row[j + 2], n3 = row[j + 3];
        float2 v0 = s[n0], v1 = s[n1], v2 = s[n2], v3 = s[n3];
        ax += v0.x; ay += v0.y;
        bx += v1.x; by += v1.y;
        cx += v2.x; cy += v2.y;
        dx += v3.x; dy += v3.y;
    }
    for (; j < n; j++) {
        float2 v = s[row[j]];
        ax += v.x; ay += v.y;
    }
    float di = g_dinv[i];
    s_ptr<K + 1>()[i] = make_float2(di * ((ax + bx) + (cx + dx)),
                                    di * ((ay + by) + (cy + dy)));
}

// Collapse the weight chain into 4 rank-1 coefficient rows (1 warp).
// R1 = W1W2W3W4 ; R2 = b1W2W3W4 ; R3 = b2W3W4 ; R4 = b3W4   (verified R12/R14)
__global__ void k_prep() {
    int j = threadIdx.x;
    if (j >= 32) return;
    float c8[8], c16[16];
#pragma unroll
    for (int m = 0; m < 8; m++) {
        float t = 0.f;
#pragma unroll
        for (int k = 0; k < 4; k++) t = fmaf(c_w[W1_OFF + k], c_w[W2_OFF + k * 8 + m], t);
        c8[m] = t;
    }
#pragma unroll
    for (int n = 0; n < 16; n++) {
        float t = 0.f;
#pragma unroll
        for (int m = 0; m < 8; m++) t = fmaf(c8[m], c_w[W3_OFF + m * 16 + n], t);
        c16[n] = t;
    }
    {
        float t = 0.f;
#pragma unroll
        for (int n = 0; n < 16; n++) t = fmaf(c16[n], c_w[W4_OFF + n * 32 + j], t);
        g_R[j] = t;
    }
#pragma unroll
    for (int m = 0; m < 8; m++) {
        float t = 0.f;
#pragma unroll
        for (int k = 0; k < 4; k++) t = fmaf(c_w[B1_OFF + k], c_w[W2_OFF + k * 8 + m], t);
        c8[m] = t;
    }
#pragma unroll
    for (int n = 0; n < 16; n++) {
        float t = 0.f;
#pragma unroll
        for (int m = 0; m < 8; m++) t = fmaf(c8[m], c_w[W3_OFF + m * 16 + n], t);
        c16[n] = t;
    }
    {
        float t = 0.f;
#pragma unroll
        for (int n = 0; n < 16; n++) t = fmaf(c16[n], c_w[W4_OFF + n * 32 + j], t);
        g_R[32 + j] = t;
    }
#pragma unroll
    for (int n = 0; n < 16; n++) {
        float t = 0.f;
#pragma unroll
        for (int m = 0; m < 8; m++) t = fmaf(c_w[B2_OFF + m], c_w[W3_OFF + m * 16 + n], t);
        c16[n] = t;
    }
    {
        float t = 0.f;
#pragma unroll
        for (int n = 0; n < 16; n++) t = fmaf(c16[n], c_w[W4_OFF + n * 32 + j], t);
        g_R[64 + j] = t;
    }
    {
        float t = 0.f;
#pragma unroll
        for (int n = 0; n < 16; n++) t = fmaf(c_w[B3_OFF + n], c_w[W4_OFF + n * 32 + j], t);
        g_R[96 + j] = t;
    }
}

// fused pass-4 + output: u4 from scalar gather of s3.x, then rank-4 GEMV row
__global__ void k_pull3out(float* __restrict__ out) {
    int i = blockIdx.x * TPB + threadIdx.x;
    if (i >= NN) return;
    int n   = min(g_cnt[i], CAP);
    const int* __restrict__ row = g_bkt + i * CAP;
    float2 s3 = g_s3[i];
    float a = s3.x, b = 0.f, c = 0.f, d = 0.f;
    int j = 0;
    for (; j + 3 < n; j += 4) {
        int n0 = row[j], n1 = row[j + 1], n2 = row[j + 2], n3 = row[j + 3];
        a += g_s3[n0].x;
        b += g_s3[n1].x;
        c += g_s3[n2].x;
        d += g_s3[n3].x;
    }
    for (; j < n; j++) a += g_s3[row[j]].x;

    float q  = g_sqd[i];
    float u4 = q * g_dinv[i] * ((a + b) + (c + d));
    float v3 = q * s3.y;
    float v2 = q * g_s2[i].y;
    float v1 = q * g_s1[i].y;
    float4* o = (float4*)(out + (size_t)i * 32);
#pragma unroll
    for (int cc = 0; cc < 8; cc++) {
        float4 r;
        float* rp = (float*)&r;
#pragma unroll
        for (int qq = 0; qq < 4; qq++) {
            int jj = 4 * cc + qq;
            float t = c_w[B4_OFF + jj];
            t = fmaf(u4, g_R[jj],      t);
            t = fmaf(v3, g_R[32 + jj], t);
            t = fmaf(v2, g_R[64 + jj], t);
            t = fmaf(v1, g_R[96 + jj], t);
            rp[qq] = t;
        }
        o[cc] = r;
    }
}

// ---------------- launch ----------------
extern "C" void kernel_launch(void* const* d_in, const int* in_sizes, int n_in,
                              void* d_out, int out_size) {
    const int* rl  = (const int*)d_in[0];
    const int* ei  = (const int*)d_in[1];
    const int* src = ei;
    const int* dst = ei + NE;

    cudaMemcpyToSymbolAsync(c_w, d_in[2],   4 * sizeof(float), W1_OFF * sizeof(float), cudaMemcpyDeviceToDevice, 0);
    cudaMemcpyToSymbolAsync(c_w, d_in[3],   4 * sizeof(float), B1_OFF * sizeof(float), cudaMemcpyDeviceToDevice, 0);
    cudaMemcpyToSymbolAsync(c_w, d_in[4],  32 * sizeof(float), W2_OFF * sizeof(float), cudaMemcpyDeviceToDevice, 0);
    cudaMemcpyToSymbolAsync(c_w, d_in[5],   8 * sizeof(float), B2_OFF * sizeof(float), cudaMemcpyDeviceToDevice, 0);
    cudaMemcpyToSymbolAsync(c_w, d_in[6], 128 * sizeof(float), W3_OFF * sizeof(float), cudaMemcpyDeviceToDevice, 0);
    cudaMemcpyToSymbolAsync(c_w, d_in[7],  16 * sizeof(float), B3_OFF * sizeof(float), cudaMemcpyDeviceToDevice, 0);
    cudaMemcpyToSymbolAsync(c_w, d_in[8], 512 * sizeof(float), W4_OFF * sizeof(float), cudaMemcpyDeviceToDevice, 0);
    cudaMemcpyToSymbolAsync(c_w, d_in[9],  32 * sizeof(float), B4_OFF * sizeof(float), cudaMemcpyDeviceToDevice, 0);

    const int nb_e = (NE + TPB - 1) / TPB;

    k_prep     <<<1,    32 >>>();
    k_zero     <<<NB_N, TPB>>>();
    k_scatter  <<<nb_e, TPB>>>(src, dst);
    k_node1    <<<NB_N, TPB>>>(rl);
    k_pull<0>  <<<NB_N, TPB>>>();
    k_pull<1>  <<<NB_N, TPB>>>();
    k_pull<2>  <<<NB_N, TPB>>>();
    k_pull3out <<<NB_N, TPB>>>((float*)d_out);
}

// round 16
// speedup vs baseline: 1.0619x; 1.0619x over previous
#include <cuda_runtime.h>

#define NN 500000
#define NE 8000000
#define TPB 256
#define NB_N ((NN + TPB - 1) / TPB)   // 1954 node blocks

// ---------------- scratch (static __device__ — no allocation) ----------------
__device__ int    g_hist[NN];      // in-degree (no self loop)
__device__ int    g_excl[NN];      // exclusive scan within block
__device__ int    g_bsum[2048];    // per-block sums
__device__ int    g_boff[2048];    // exclusive-scanned block offsets
__device__ int    g_row [NN];      // CSR row starts
__device__ int    g_cur [NN];      // scatter cursors
__device__ int    g_csr [NE];      // src indices grouped by dst (32 MB — L2-resident)
__device__ float  g_dinv[NN];      // 1/(deg+1)
__device__ float  g_sqd [NN];      // sqrt(deg+1)
__device__ float2 g_s0[NN], g_s1[NN], g_s2[NN], g_s3[NN];  // s_k = dsr*(u_k, v_k)
__device__ float  g_R  [128];      // R1,R2,R3,R4 (each 32) — collapsed weight rows

// ---------------- weights in constant memory ----------------
__constant__ float c_w[736];
#define W1_OFF 0
#define B1_OFF 4
#define W2_OFF 8
#define B2_OFF 40
#define W3_OFF 48
#define B3_OFF 176
#define W4_OFF 192
#define B4_OFF 704

// Compile-time s_k selection (device-side symbol refs only — R8 lesson).
template<int K> __device__ __forceinline__ float2* s_ptr() {
    if (K == 0) return g_s0;
    if (K == 1) return g_s1;
    if (K == 2) return g_s2;
    return g_s3;
}

// ---------------- kernels ----------------
__global__ void k_zero() {
    int i = blockIdx.x * TPB + threadIdx.x;
    if (i < NN) g_hist[i] = 0;
}

__global__ void k_deg(const int* __restrict__ dst) {
    int e = blockIdx.x * TPB + threadIdx.x;
    if (e < NE) atomicAdd(&g_hist[e < NE ? dst[e] : 0], 1);
}

// block-wise exclusive scan of g_hist
__global__ void k_scan1() {
    __shared__ int bufA[TPB], bufB[TPB];
    int t = threadIdx.x;
    int i = blockIdx.x * TPB + t;
    bufA[t] = (i < NN) ? g_hist[i] : 0;
    __syncthreads();
    int* in = bufA; int* out = bufB;
#pragma unroll
    for (int off = 1; off < TPB; off <<= 1) {
        out[t] = in[t] + (t >= off ? in[t - off] : 0);
        __syncthreads();
        int* tmp = in; in = out; out = tmp;
    }
    if (i < NN) g_excl[i] = (t ? in[t - 1] : 0);
    if (t == TPB - 1) g_bsum[blockIdx.x] = in[t];
}

// single-block exclusive scan of 1954 block sums (padded to 2048)
__global__ void k_scan2() {
    __shared__ int bufA[2048], bufB[2048];
    int t = threadIdx.x;                      // 1024 threads
    for (int k = t; k < 2048; k += 1024) bufA[k] = (k < NB_N) ? g_bsum[k] : 0;
    __syncthreads();
    int* in = bufA; int* out = bufB;
#pragma unroll
    for (int off = 1; off < 2048; off <<= 1) {
        for (int k = t; k < 2048; k += 1024)
            out[k] = in[k] + (k >= off ? in[k - off] : 0);
        __syncthreads();
        int* tmp = in; in = out; out = tmp;
    }
    for (int k = t; k < NB_N; k += 1024) g_boff[k] = (k ? in[k - 1] : 0);
}

// row starts + cursors + degree terms + s0 ; fuses scan level-3
__global__ void k_node1(const int* __restrict__ rl) {
    int i = blockIdx.x * TPB + threadIdx.x;
    if (i >= NN) return;
    int row = g_excl[i] + g_boff[blockIdx.x];
    g_row[i] = row;
    g_cur[i] = row;
    float deg = (float)g_hist[i] + 1.0f;
    float ds  = rsqrtf(deg);
    g_dinv[i] = 1.0f / deg;
    g_sqd[i]  = sqrtf(deg);
    g_s0[i]   = make_float2((float)rl[i] * (1.0f / 20000.0f) * ds, ds);
}

// counting-sort scatter: group src indices by dst
__global__ void k_scatter(const int* __restrict__ src, const int* __restrict__ dst) {
    int e = blockIdx.x * TPB + threadIdx.x;
    if (e >= NE) return;
    int p = atomicAdd(&g_cur[dst[e]], 1);
    g_csr[p] = src[e];
}

// pull pass K: s_{K+1}[i] = dinv_i * (s_K[i] + sum_{j->i} s_K[j]) — no atomics
template<int K>
__global__ void k_pull() {
    int i = blockIdx.x * TPB + threadIdx.x;
    if (i >= NN) return;
    const float2* __restrict__ s = s_ptr<K>();
    int beg = g_row[i];
    int end = beg + g_hist[i];
    float2 self = s[i];
    float ax = self.x, ay = self.y;
    float bx = 0.f, by = 0.f, cx = 0.f, cy = 0.f, dx = 0.f, dy = 0.f;
    int j = beg;
    for (; j + 3 < end; j += 4) {                 // 4-way MLP
        int n0 = g_csr[j], n1 = g_csr[j + 1], n2 = g_csr[j + 2], n3 = g_csr[j + 3];
        float2 v0 = s[n0], v1 = s[n1], v2 = s[n2], v3 = s[n3];
        ax += v0.x; ay += v0.y;
        bx += v1.x; by += v1.y;
        cx += v2.x; cy += v2.y;
        dx += v3.x; dy += v3.y;
    }
    for (; j < end; j++) {
        float2 v = s[g_csr[j]];
        ax += v.x; ay += v.y;
    }
    float di = g_dinv[i];
    s_ptr<K + 1>()[i] = make_float2(di * ((ax + bx) + (cx + dx)),
                                    di * ((ay + by) + (cy + dy)));
}

// Collapse the weight chain into 4 rank-1 coefficient rows (1 warp).
// R1 = W1W2W3W4 ; R2 = b1W2W3W4 ; R3 = b2W3W4 ; R4 = b3W4   (verified R12/R14)
__global__ void k_prep() {
    int j = threadIdx.x;
    if (j >= 32) return;
    float c8[8], c16[16];
#pragma unroll
    for (int m = 0; m < 8; m++) {
        float t = 0.f;
#pragma unroll
        for (int k = 0; k < 4; k++) t = fmaf(c_w[W1_OFF + k], c_w[W2_OFF + k * 8 + m], t);
        c8[m] = t;
    }
#pragma unroll
    for (int n = 0; n < 16; n++) {
        float t = 0.f;
#pragma unroll
        for (int m = 0; m < 8; m++) t = fmaf(c8[m], c_w[W3_OFF + m * 16 + n], t);
        c16[n] = t;
    }
    {
        float t = 0.f;
#pragma unroll
        for (int n = 0; n < 16; n++) t = fmaf(c16[n], c_w[W4_OFF + n * 32 + j], t);
        g_R[j] = t;
    }
#pragma unroll
    for (int m = 0; m < 8; m++) {
        float t = 0.f;
#pragma unroll
        for (int k = 0; k < 4; k++) t = fmaf(c_w[B1_OFF + k], c_w[W2_OFF + k * 8 + m], t);
        c8[m] = t;
    }
#pragma unroll
    for (int n = 0; n < 16; n++) {
        float t = 0.f;
#pragma unroll
        for (int m = 0; m < 8; m++) t = fmaf(c8[m], c_w[W3_OFF + m * 16 + n], t);
        c16[n] = t;
    }
    {
        float t = 0.f;
#pragma unroll
        for (int n = 0; n < 16; n++) t = fmaf(c16[n], c_w[W4_OFF + n * 32 + j], t);
        g_R[32 + j] = t;
    }
#pragma unroll
    for (int n = 0; n < 16; n++) {
        float t = 0.f;
#pragma unroll
        for (int m = 0; m < 8; m++) t = fmaf(c_w[B2_OFF + m], c_w[W3_OFF + m * 16 + n], t);
        c16[n] = t;
    }
    {
        float t = 0.f;
#pragma unroll
        for (int n = 0; n < 16; n++) t = fmaf(c16[n], c_w[W4_OFF + n * 32 + j], t);
        g_R[64 + j] = t;
    }
    {
        float t = 0.f;
#pragma unroll
        for (int n = 0; n < 16; n++) t = fmaf(c_w[B3_OFF + n], c_w[W4_OFF + n * 32 + j], t);
        g_R[96 + j] = t;
    }
}

// fused pass-4 + output: u4 from scalar gather of s3.x, then rank-4 GEMV row
__global__ void k_pull3out(float* __restrict__ out) {
    int i = blockIdx.x * TPB + threadIdx.x;
    if (i >= NN) return;
    int beg = g_row[i];
    int end = beg + g_hist[i];
    float2 s3 = g_s3[i];
    float a = s3.x, b = 0.f, c = 0.f, d = 0.f;
    int j = beg;
    for (; j + 3 < end; j += 4) {
        int n0 = g_csr[j], n1 = g_csr[j + 1], n2 = g_csr[j + 2], n3 = g_csr[j + 3];
        a += g_s3[n0].x;
        b += g_s3[n1].x;
        c += g_s3[n2].x;
        d += g_s3[n3].x;
    }
    for (; j < end; j++) a += g_s3[g_csr[j]].x;

    float q  = g_sqd[i];
    float u4 = q * g_dinv[i] * ((a + b) + (c + d));
    float v3 = q * s3.y;
    float v2 = q * g_s2[i].y;
    float v1 = q * g_s1[i].y;
    float4* o = (float4*)(out + (size_t)i * 32);
#pragma unroll
    for (int cc = 0; cc < 8; cc++) {
        float4 r;
        float* rp = (float*)&r;
#pragma unroll
        for (int qq = 0; qq < 4; qq++) {
            int jj = 4 * cc + qq;
            float t = c_w[B4_OFF + jj];
            t = fmaf(u4, g_R[jj],      t);
            t = fmaf(v3, g_R[32 + jj], t);
            t = fmaf(v2, g_R[64 + jj], t);
            t = fmaf(v1, g_R[96 + jj], t);
            rp[qq] = t;
        }
        o[cc] = r;
    }
}

// ---------------- launch ----------------
extern "C" void kernel_launch(void* const* d_in, const int* in_sizes, int n_in,
                              void* d_out, int out_size) {
    const int* rl  = (const int*)d_in[0];
    const int* ei  = (const int*)d_in[1];
    const int* src = ei;
    const int* dst = ei + NE;

    cudaMemcpyToSymbolAsync(c_w, d_in[2],   4 * sizeof(float), W1_OFF * sizeof(float), cudaMemcpyDeviceToDevice, 0);
    cudaMemcpyToSymbolAsync(c_w, d_in[3],   4 * sizeof(float), B1_OFF * sizeof(float), cudaMemcpyDeviceToDevice, 0);
    cudaMemcpyToSymbolAsync(c_w, d_in[4],  32 * sizeof(float), W2_OFF * sizeof(float), cudaMemcpyDeviceToDevice, 0);
    cudaMemcpyToSymbolAsync(c_w, d_in[5],   8 * sizeof(float), B2_OFF * sizeof(float), cudaMemcpyDeviceToDevice, 0);
    cudaMemcpyToSymbolAsync(c_w, d_in[6], 128 * sizeof(float), W3_OFF * sizeof(float), cudaMemcpyDeviceToDevice, 0);
    cudaMemcpyToSymbolAsync(c_w, d_in[7],  16 * sizeof(float), B3_OFF * sizeof(float), cudaMemcpyDeviceToDevice, 0);
    cudaMemcpyToSymbolAsync(c_w, d_in[8], 512 * sizeof(float), W4_OFF * sizeof(float), cudaMemcpyDeviceToDevice, 0);
    cudaMemcpyToSymbolAsync(c_w, d_in[9],  32 * sizeof(float), B4_OFF * sizeof(float), cudaMemcpyDeviceToDevice, 0);

    const int nb_e = (NE + TPB - 1) / TPB;

    k_prep    <<<1,    32  >>>();
    k_zero    <<<NB_N, TPB >>>();
    k_deg     <<<nb_e, TPB >>>(dst);
    k_scan1   <<<NB_N, TPB >>>();
    k_scan2   <<<1,    1024>>>();
    k_node1   <<<NB_N, TPB >>>(rl);
    k_scatter <<<nb_e, TPB >>>(src, dst);
    k_pull<0> <<<NB_N, TPB >>>();
    k_pull<1> <<<NB_N, TPB >>>();
    k_pull<2> <<<NB_N, TPB >>>();
    k_pull3out<<<NB_N, TPB >>>((float*)d_out);
}

// round 17
// speedup vs baseline: 1.1349x; 1.0687x over previous
#include <cuda_runtime.h>

#define NN 500000
#define NE 8000000
#define TPB 256
#define NB_N ((NN + TPB - 1) / TPB)

#define BSH   7                    // 128 nodes per bin
#define BINS  3907                 // ceil(NN / 128)
#define BINP  3968                 // padded bin count (smem arrays)
#define SCANP 4096                 // pow2 pad for bin scan
#define SCG   296                  // edge-chunk grid (2 waves of 148)
#define CHUNK ((NE + SCG - 1) / SCG)   // 27028 edges per block
#define BCAP  3072                 // bin smem capacity (mean 2048, sigma 45)

// ---------------- scratch (static __device__ — no allocation) ----------------
__device__ int      g_binh[SCANP];     // bin totals
__device__ int      g_bino[SCANP];     // bin base offsets (exclusive scan)
__device__ int      g_binc[SCANP];     // bin reservation cursors
__device__ unsigned g_binned[NE];      // packed (dstLow7 << 19) | src
__device__ int      g_hist[NN];        // in-degree
__device__ int      g_row [NN];        // CSR row starts
__device__ int      g_csr [NE];        // src indices grouped by dst (32 MB)
__device__ float    g_dinv[NN];        // 1/(deg+1)
__device__ float    g_sqd [NN];        // sqrt(deg+1)
__device__ float2   g_s0[NN], g_s1[NN], g_s2[NN], g_s3[NN];  // s_k = dsr*(u_k, v_k)
__device__ float    g_R  [128];        // collapsed weight rows R1..R4

// ---------------- weights in constant memory ----------------
__constant__ float c_w[736];
#define W1_OFF 0
#define B1_OFF 4
#define W2_OFF 8
#define B2_OFF 40
#define W3_OFF 48
#define B3_OFF 176
#define W4_OFF 192
#define B4_OFF 704

// Compile-time s_k selection (device-side symbol refs only — R8 lesson).
template<int K> __device__ __forceinline__ float2* s_ptr() {
    if (K == 0) return g_s0;
    if (K == 1) return g_s1;
    if (K == 2) return g_s2;
    return g_s3;
}

// ---------------- CSR build: binned counting sort ----------------
__global__ void k_zerobins() {
    int i = blockIdx.x * TPB + threadIdx.x;
    if (i < SCANP) g_binh[i] = 0;
}

// phase 1: global bin histogram via per-block smem histogram
__global__ void k_binhist(const int* __restrict__ dst) {
    __shared__ int h[BINP];
    for (int k = threadIdx.x; k < BINP; k += TPB) h[k] = 0;
    __syncthreads();
    int beg = blockIdx.x * CHUNK;
    int end = min(NE, beg + CHUNK);
    for (int e = beg + threadIdx.x; e < end; e += TPB)
        atomicAdd(&h[dst[e] >> BSH], 1);
    __syncthreads();
    for (int k = threadIdx.x; k < BINS; k += TPB)
        if (h[k]) atomicAdd(&g_binh[k], h[k]);
}

// phase 2: exclusive scan of bin totals (single block); init cursors
__global__ void k_binscan() {
    __shared__ int bufA[SCANP], bufB[SCANP];
    int t = threadIdx.x;                       // 1024 threads
    for (int k = t; k < SCANP; k += 1024) bufA[k] = g_binh[k];
    __syncthreads();
    int* in = bufA; int* out = bufB;
#pragma unroll
    for (int off = 1; off < SCANP; off <<= 1) {
        for (int k = t; k < SCANP; k += 1024)
            out[k] = in[k] + (k >= off ? in[k - off] : 0);
        __syncthreads();
        int* tmp = in; in = out; out = tmp;
    }
    for (int k = t; k < BINS; k += 1024) {
        int base = (k ? in[k - 1] : 0);
        g_bino[k] = base;
        g_binc[k] = base;
    }
}

// phase 3: bin the edges (packed records) with one reservation atomic per (block,bin)
__global__ void k_binscatter(const int* __restrict__ src, const int* __restrict__ dst) {
    __shared__ int cnt[BINP];
    __shared__ int cur[BINP];
    for (int k = threadIdx.x; k < BINP; k += TPB) cnt[k] = 0;
    __syncthreads();
    int beg = blockIdx.x * CHUNK;
    int end = min(NE, beg + CHUNK);
    for (int e = beg + threadIdx.x; e < end; e += TPB)
        atomicAdd(&cnt[dst[e] >> BSH], 1);
    __syncthreads();
    for (int k = threadIdx.x; k < BINS; k += TPB)
        if (cnt[k]) cur[k] = atomicAdd(&g_binc[k], cnt[k]);
    __syncthreads();
    for (int e = beg + threadIdx.x; e < end; e += TPB) {
        int d = dst[e];
        int b = d >> BSH;
        int p = atomicAdd(&cur[b], 1);
        g_binned[p] = ((unsigned)(d & 127) << 19) | (unsigned)src[e];
    }
}

// phase 4: per-bin smem counting sort -> CSR; fused per-node init
__global__ void k_binsort(const int* __restrict__ rl) {
    __shared__ unsigned recs[BCAP];
    __shared__ int      sorted[BCAP];
    __shared__ int      cnt[128], start[128], cur[128];
    int b    = blockIdx.x;
    int base = g_bino[b];
    int n    = min(g_binh[b], BCAP);
    int t    = threadIdx.x;
    for (int k = t; k < n; k += TPB) recs[k] = g_binned[base + k];
    if (t < 128) cnt[t] = 0;
    __syncthreads();
    for (int k = t; k < n; k += TPB) atomicAdd(&cnt[recs[k] >> 19], 1);
    __syncthreads();
    if (t == 0) {
        int acc = 0;
#pragma unroll 8
        for (int k = 0; k < 128; k++) { start[k] = acc; acc += cnt[k]; }
    }
    __syncthreads();
    if (t < 128) cur[t] = start[t];
    __syncthreads();
    for (int k = t; k < n; k += TPB) {
        unsigned r = recs[k];
        int p = atomicAdd(&cur[r >> 19], 1);
        sorted[p] = (int)(r & 0x7FFFFu);
    }
    __syncthreads();
    for (int k = t; k < n; k += TPB) g_csr[base + k] = sorted[k];
    int node0 = b << BSH;
    if (t < 128 && node0 + t < NN) {
        int i = node0 + t;
        g_row[i]  = base + start[t];
        g_hist[i] = cnt[t];
        float deg = (float)cnt[t] + 1.0f;
        float ds  = rsqrtf(deg);
        g_dinv[i] = 1.0f / deg;
        g_sqd[i]  = sqrtf(deg);
        g_s0[i]   = make_float2((float)rl[i] * (1.0f / 20000.0f) * ds, ds);
    }
}

// ---------------- pull passes (verified R14/R16) ----------------
template<int K>
__global__ void k_pull() {
    int i = blockIdx.x * TPB + threadIdx.x;
    if (i >= NN) return;
    const float2* __restrict__ s = s_ptr<K>();
    int beg = g_row[i];
    int end = beg + g_hist[i];
    float2 self = s[i];
    float ax = self.x, ay = self.y;
    float bx = 0.f, by = 0.f, cx = 0.f, cy = 0.f, dx = 0.f, dy = 0.f;
    int j = beg;
    for (; j + 3 < end; j += 4) {
        int n0 = g_csr[j], n1 = g_csr[j + 1], n2 = g_csr[j + 2], n3 = g_csr[j + 3];
        float2 v0 = s[n0], v1 = s[n1], v2 = s[n2], v3 = s[n3];
        ax += v0.x; ay += v0.y;
        bx += v1.x; by += v1.y;
        cx += v2.x; cy += v2.y;
        dx += v3.x; dy += v3.y;
    }
    for (; j < end; j++) {
        float2 v = s[g_csr[j]];
        ax += v.x; ay += v.y;
    }
    float di = g_dinv[i];
    s_ptr<K + 1>()[i] = make_float2(di * ((ax + bx) + (cx + dx)),
                                    di * ((ay + by) + (cy + dy)));
}

// Collapse the weight chain into 4 rank-1 coefficient rows (verified R12+).
__global__ void k_prep() {
    int j = threadIdx.x;
    if (j >= 32) return;
    float c8[8], c16[16];
#pragma unroll
    for (int m = 0; m < 8; m++) {
        float t = 0.f;
#pragma unroll
        for (int k = 0; k < 4; k++) t = fmaf(c_w[W1_OFF + k], c_w[W2_OFF + k * 8 + m], t);
        c8[m] = t;
    }
#pragma unroll
    for (int n = 0; n < 16; n++) {
        float t = 0.f;
#pragma unroll
        for (int m = 0; m < 8; m++) t = fmaf(c8[m], c_w[W3_OFF + m * 16 + n], t);
        c16[n] = t;
    }
    {
        float t = 0.f;
#pragma unroll
        for (int n = 0; n < 16; n++) t = fmaf(c16[n], c_w[W4_OFF + n * 32 + j], t);
        g_R[j] = t;
    }
#pragma unroll
    for (int m = 0; m < 8; m++) {
        float t = 0.f;
#pragma unroll
        for (int k = 0; k < 4; k++) t = fmaf(c_w[B1_OFF + k], c_w[W2_OFF + k * 8 + m], t);
        c8[m] = t;
    }
#pragma unroll
    for (int n = 0; n < 16; n++) {
        float t = 0.f;
#pragma unroll
        for (int m = 0; m < 8; m++) t = fmaf(c8[m], c_w[W3_OFF + m * 16 + n], t);
        c16[n] = t;
    }
    {
        float t = 0.f;
#pragma unroll
        for (int n = 0; n < 16; n++) t = fmaf(c16[n], c_w[W4_OFF + n * 32 + j], t);
        g_R[32 + j] = t;
    }
#pragma unroll
    for (int n = 0; n < 16; n++) {
        float t = 0.f;
#pragma unroll
        for (int m = 0; m < 8; m++) t = fmaf(c_w[B2_OFF + m], c_w[W3_OFF + m * 16 + n], t);
        c16[n] = t;
    }
    {
        float t = 0.f;
#pragma unroll
        for (int n = 0; n < 16; n++) t = fmaf(c16[n], c_w[W4_OFF + n * 32 + j], t);
        g_R[64 + j] = t;
    }
    {
        float t = 0.f;
#pragma unroll
        for (int n = 0; n < 16; n++) t = fmaf(c_w[B3_OFF + n], c_w[W4_OFF + n * 32 + j], t);
        g_R[96 + j] = t;
    }
}

// fused pass-4 + output (verified R16)
__global__ void k_pull3out(float* __restrict__ out) {
    int i = blockIdx.x * TPB + threadIdx.x;
    if (i >= NN) return;
    int beg = g_row[i];
    int end = beg + g_hist[i];
    float2 s3 = g_s3[i];
    float a = s3.x, b = 0.f, c = 0.f, d = 0.f;
    int j = beg;
    for (; j + 3 < end; j += 4) {
        int n0 = g_csr[j], n1 = g_csr[j + 1], n2 = g_csr[j + 2], n3 = g_csr[j + 3];
        a += g_s3[n0].x;
        b += g_s3[n1].x;
        c += g_s3[n2].x;
        d += g_s3[n3].x;
    }
    for (; j < end; j++) a += g_s3[g_csr[j]].x;

    float q  = g_sqd[i];
    float u4 = q * g_dinv[i] * ((a + b) + (c + d));
    float v3 = q * s3.y;
    float v2 = q * g_s2[i].y;
    float v1 = q * g_s1[i].y;
    float4* o = (float4*)(out + (size_t)i * 32);
#pragma unroll
    for (int cc = 0; cc < 8; cc++) {
        float4 r;
        float* rp = (float*)&r;
#pragma unroll
        for (int qq = 0; qq < 4; qq++) {
            int jj = 4 * cc + qq;
            float t = c_w[B4_OFF + jj];
            t = fmaf(u4, g_R[jj],      t);
            t = fmaf(v3, g_R[32 + jj], t);
            t = fmaf(v2, g_R[64 + jj], t);
            t = fmaf(v1, g_R[96 + jj], t);
            rp[qq] = t;
        }
        o[cc] = r;
    }
}

// ---------------- launch ----------------
extern "C" void kernel_launch(void* const* d_in, const int* in_sizes, int n_in,
                              void* d_out, int out_size) {
    const int* rl  = (const int*)d_in[0];
    const int* ei  = (const int*)d_in[1];
    const int* src = ei;
    const int* dst = ei + NE;

    cudaMemcpyToSymbolAsync(c_w, d_in[2],   4 * sizeof(float), W1_OFF * sizeof(float), cudaMemcpyDeviceToDevice, 0);
    cudaMemcpyToSymbolAsync(c_w, d_in[3],   4 * sizeof(float), B1_OFF * sizeof(float), cudaMemcpyDeviceToDevice, 0);
    cudaMemcpyToSymbolAsync(c_w, d_in[4],  32 * sizeof(float), W2_OFF * sizeof(float), cudaMemcpyDeviceToDevice, 0);
    cudaMemcpyToSymbolAsync(c_w, d_in[5],   8 * sizeof(float), B2_OFF * sizeof(float), cudaMemcpyDeviceToDevice, 0);
    cudaMemcpyToSymbolAsync(c_w, d_in[6], 128 * sizeof(float), W3_OFF * sizeof(float), cudaMemcpyDeviceToDevice, 0);
    cudaMemcpyToSymbolAsync(c_w, d_in[7],  16 * sizeof(float), B3_OFF * sizeof(float), cudaMemcpyDeviceToDevice, 0);
    cudaMemcpyToSymbolAsync(c_w, d_in[8], 512 * sizeof(float), W4_OFF * sizeof(float), cudaMemcpyDeviceToDevice, 0);
    cudaMemcpyToSymbolAsync(c_w, d_in[9],  32 * sizeof(float), B4_OFF * sizeof(float), cudaMemcpyDeviceToDevice, 0);

    k_prep      <<<1,    32  >>>();
    k_zerobins  <<<(SCANP + TPB - 1) / TPB, TPB>>>();
    k_binhist   <<<SCG,  TPB >>>(dst);
    k_binscan   <<<1,    1024>>>();
    k_binscatter<<<SCG,  TPB >>>(src, dst);
    k_binsort   <<<BINS, TPB >>>(rl);
    k_pull<0>   <<<NB_N, TPB >>>();
    k_pull<1>   <<<NB_N, TPB >>>();
    k_pull<2>   <<<NB_N, TPB >>>();
    k_pull3out  <<<NB_N, TPB >>>((float*)d_out);
}